// round 4
// baseline (speedup 1.0000x reference)
#include <cuda_runtime.h>
#include <math.h>

#define HIDDEN  4096
#define NEXP    128
#define TOPK    8
#define BM      64
#define BN      128
#define BK      32
#define BMP     65     // As row pad: conflict-free transpose STS, scalar reads
#define BNP     132    // Bs row pad: multiple of 4 for 16B-aligned vector reads

typedef unsigned long long u64;

__device__ __forceinline__ u64 pk2(float lo, float hi) {
    u64 r; asm("mov.b64 %0, {%1, %2};" : "=l"(r) : "f"(lo), "f"(hi)); return r;
}
__device__ __forceinline__ void upk2(u64 v, float& lo, float& hi) {
    asm("mov.b64 {%0, %1}, %2;" : "=f"(lo), "=f"(hi) : "l"(v));
}
// Packed dual FMA: d.lo += a.lo*b.lo ; d.hi += a.hi*b.hi  (FFMA2, PTX-only)
__device__ __forceinline__ void fma2(u64& d, u64 a, u64 b) {
    asm("fma.rn.f32x2 %0, %1, %2, %0;" : "+l"(d) : "l"(a), "l"(b));
}

// One block: BM=64 tokens x all 128 experts, K-loop over HIDDEN.
// Thread (tx = tid&15, ty = tid>>4) owns tokens [ty*4, ty*4+4) x experts [tx*8, tx*8+8).
// A warp = 2 half-warps; each half-warp (fixed ty) holds 4 full token rows ->
// top-k runs on registers with width-16 shuffles, no epilogue smem.
__global__ __launch_bounds__(256, 2)
void router_topk_kernel(const float* __restrict__ h,
                        const float* __restrict__ W,
                        const float* __restrict__ bias,
                        float* __restrict__ outI,
                        float* __restrict__ outW)
{
    __shared__ float As[BK][BMP];   // k-major token tile
    __shared__ float Bs[BK][BNP];   // k-major expert tile
    __shared__ float bias_s[NEXP];

    const int tid = threadIdx.x;
    const int tx  = tid & 15;
    const int ty  = tid >> 4;
    const int m0  = blockIdx.x * BM;

    if (tid < NEXP) bias_s[tid] = bias[tid];

    u64 acc[4][4];
    #pragma unroll
    for (int i = 0; i < 4; i++)
        #pragma unroll
        for (int p = 0; p < 4; p++) acc[i][p] = pk2(0.f, 0.f);

    // Per-thread load slots (float4 along K, transposed on STS)
    int aRow[2], aKq[2];
    #pragma unroll
    for (int j = 0; j < 2; j++) { int lin = tid + 256 * j; aRow[j] = lin >> 3; aKq[j] = lin & 7; }
    int bRow[4], bKq[4];
    #pragma unroll
    for (int j = 0; j < 4; j++) { int lin = tid + 256 * j; bRow[j] = lin >> 3; bKq[j] = lin & 7; }

    float4 aReg[2], bReg[4];

    // Preload stage 0
    #pragma unroll
    for (int j = 0; j < 2; j++)
        aReg[j] = *(const float4*)(h + (size_t)(m0 + aRow[j]) * HIDDEN + aKq[j] * 4);
    #pragma unroll
    for (int j = 0; j < 4; j++)
        bReg[j] = *(const float4*)(W + (size_t)bRow[j] * HIDDEN + bKq[j] * 4);

    const int NSTAGE = HIDDEN / BK;
    for (int s = 0; s < NSTAGE; s++) {
        // Transpose-store staged registers into smem
        #pragma unroll
        for (int j = 0; j < 2; j++) {
            As[aKq[j] * 4 + 0][aRow[j]] = aReg[j].x;
            As[aKq[j] * 4 + 1][aRow[j]] = aReg[j].y;
            As[aKq[j] * 4 + 2][aRow[j]] = aReg[j].z;
            As[aKq[j] * 4 + 3][aRow[j]] = aReg[j].w;
        }
        #pragma unroll
        for (int j = 0; j < 4; j++) {
            Bs[bKq[j] * 4 + 0][bRow[j]] = bReg[j].x;
            Bs[bKq[j] * 4 + 1][bRow[j]] = bReg[j].y;
            Bs[bKq[j] * 4 + 2][bRow[j]] = bReg[j].z;
            Bs[bKq[j] * 4 + 3][bRow[j]] = bReg[j].w;
        }
        __syncthreads();

        // Prefetch next stage's tiles into registers (overlaps with FMA below)
        if (s + 1 < NSTAGE) {
            const int k0 = (s + 1) * BK;
            #pragma unroll
            for (int j = 0; j < 2; j++)
                aReg[j] = *(const float4*)(h + (size_t)(m0 + aRow[j]) * HIDDEN + k0 + aKq[j] * 4);
            #pragma unroll
            for (int j = 0; j < 4; j++)
                bReg[j] = *(const float4*)(W + (size_t)bRow[j] * HIDDEN + k0 + bKq[j] * 4);
        }

        // Inner product: 16 f32x2 FMAs per k-step per thread
        #pragma unroll
        for (int k = 0; k < BK; k++) {
            const float a0 = As[k][ty * 4 + 0];
            const float a1 = As[k][ty * 4 + 1];
            const float a2 = As[k][ty * 4 + 2];
            const float a3 = As[k][ty * 4 + 3];
            const ulonglong2 bb0 = *(const ulonglong2*)&Bs[k][tx * 8];
            const ulonglong2 bb1 = *(const ulonglong2*)&Bs[k][tx * 8 + 4];
            u64 aa;
            aa = pk2(a0, a0);
            fma2(acc[0][0], aa, bb0.x); fma2(acc[0][1], aa, bb0.y);
            fma2(acc[0][2], aa, bb1.x); fma2(acc[0][3], aa, bb1.y);
            aa = pk2(a1, a1);
            fma2(acc[1][0], aa, bb0.x); fma2(acc[1][1], aa, bb0.y);
            fma2(acc[1][2], aa, bb1.x); fma2(acc[1][3], aa, bb1.y);
            aa = pk2(a2, a2);
            fma2(acc[2][0], aa, bb0.x); fma2(acc[2][1], aa, bb0.y);
            fma2(acc[2][2], aa, bb1.x); fma2(acc[2][3], aa, bb1.y);
            aa = pk2(a3, a3);
            fma2(acc[3][0], aa, bb0.x); fma2(acc[3][1], aa, bb0.y);
            fma2(acc[3][2], aa, bb1.x); fma2(acc[3][3], aa, bb1.y);
        }
        __syncthreads();
    }

    // ---- Epilogue: sigmoid + bias, top-8 (tie -> lowest index), normalize ----
    const unsigned FULL = 0xffffffffu;
    #pragma unroll
    for (int i = 0; i < 4; i++) {
        float sc[8];
        #pragma unroll
        for (int p = 0; p < 4; p++) {
            float lo, hi; upk2(acc[i][p], lo, hi);
            sc[2 * p] = lo; sc[2 * p + 1] = hi;
        }
        // corrected score = sigmoid(logit) + bias  (raw recovered as corrected - bias)
        #pragma unroll
        for (int j = 0; j < 8; j++) {
            float sig = 1.0f / (1.0f + expf(-sc[j]));
            sc[j] = sig + bias_s[tx * 8 + j];
        }

        float rem[8];
        #pragma unroll
        for (int j = 0; j < 8; j++) rem[j] = sc[j];

        int   topi[TOPK];
        float topraw[TOPK];
        float denom = 1e-20f;

        #pragma unroll
        for (int sel = 0; sel < TOPK; sel++) {
            // local argmax over this lane's 8 experts (strict > keeps lowest index)
            float bv = -3.4e38f; int bi = NEXP;
            #pragma unroll
            for (int j = 0; j < 8; j++)
                if (rem[j] > bv) { bv = rem[j]; bi = tx * 8 + j; }
            // half-warp (width 16) argmax reduce, tie -> lower expert index
            #pragma unroll
            for (int off = 8; off; off >>= 1) {
                float ov = __shfl_xor_sync(FULL, bv, off, 16);
                int   oi = __shfl_xor_sync(FULL, bi, off, 16);
                if (ov > bv || (ov == bv && oi < bi)) { bv = ov; bi = oi; }
            }
            topi[sel]   = bi;
            float raw   = bv - bias_s[bi];
            topraw[sel] = raw;
            denom      += raw;
            const int lj = bi - tx * 8;
            if (lj >= 0 && lj < 8) rem[lj] = -3.4e38f;
        }

        if (tx == 0) {
            const size_t t = (size_t)(m0 + ty * 4 + i);
            const float inv = 1.0f / denom;
            #pragma unroll
            for (int sel = 0; sel < TOPK; sel++) {
                outI[t * TOPK + sel] = (float)topi[sel];
                outW[t * TOPK + sel] = topraw[sel] * inv;
            }
        }
    }
}

extern "C" void kernel_launch(void* const* d_in, const int* in_sizes, int n_in,
                              void* d_out, int out_size)
{
    const float* h    = (const float*)d_in[0];   // hidden_states [B,S,H] fp32
    const float* W    = (const float*)d_in[1];   // weight [E,H] fp32
    const float* bias = (const float*)d_in[2];   // e_score_correction_bias [E]

    const int T = in_sizes[0] / HIDDEN;          // 16384 tokens

    // Output: tuple (topk_indices, topk_weights) flattened & concatenated as fp32
    float* out  = (float*)d_out;
    float* outI = out;
    float* outW = out + (size_t)T * TOPK;

    dim3 grid(T / BM);
    router_topk_kernel<<<grid, 256>>>(h, W, bias, outI, outW);
}

// round 6
// speedup vs baseline: 1.6465x; 1.6465x over previous
#include <cuda_runtime.h>
#include <cstdint>
#include <math.h>

#define HIDDEN  4096
#define NEXP    128
#define TOPK    8
#define BM      64
#define BN      128
#define BK      32
#define BKP     33      // As row pad: conflict-free scalar A-frag reads & STS
#define BNP     132     // Bs row pad: keeps LDS.128 16B-aligned, conflict-free
#define THREADS 128
#define NSTAGE  (HIDDEN / BK)

// Per-stage smem footprints (floats)
#define AS_STAGE (BM * BKP)       // 2112
#define BS_STAGE (BK * BNP)       // 4224
#define SMEM_FLOATS (2*AS_STAGE + 2*BS_STAGE + NEXP)   // 12800 -> 51200 B
#define AS(buf,m,k)  sm_As[(buf)*AS_STAGE + (m)*BKP + (k)]
#define BS(buf,k,e)  sm_Bs[(buf)*BS_STAGE + (k)*BNP + (e)]

typedef unsigned long long u64;

// k-major transposed router weight: Wt[k][e]
__device__ float g_Wt[HIDDEN * NEXP];

__device__ __forceinline__ u64 pk2(float lo, float hi) {
    u64 r; asm("mov.b64 %0, {%1, %2};" : "=l"(r) : "f"(lo), "f"(hi)); return r;
}
__device__ __forceinline__ void upk2(u64 v, float& lo, float& hi) {
    asm("mov.b64 {%0, %1}, %2;" : "=f"(lo), "=f"(hi) : "l"(v));
}
// Packed dual FMA: d.lo += a.lo*b.lo ; d.hi += a.hi*b.hi  (FFMA2, PTX-only)
__device__ __forceinline__ void fma2(u64& d, u64 a, u64 b) {
    asm("fma.rn.f32x2 %0, %1, %2, %0;" : "+l"(d) : "l"(a), "l"(b));
}
__device__ __forceinline__ void cp16(uint32_t dst, const void* src) {
    asm volatile("cp.async.cg.shared.global [%0], [%1], 16;\n" :: "r"(dst), "l"(src));
}
#define CP_COMMIT() asm volatile("cp.async.commit_group;\n" ::: "memory")
#define CP_WAIT0()  asm volatile("cp.async.wait_group 0;\n"  ::: "memory")

// ---- W transpose: g_Wt[k][e] = W[e][k]  (runs once per launch, ~3us) ----
__global__ void transpose_w_kernel(const float* __restrict__ W) {
    __shared__ float t[32][33];
    const int k0 = blockIdx.x * 32, e0 = blockIdx.y * 32;
    const int x = threadIdx.x & 31, y = threadIdx.x >> 5;   // 256 thr: y 0..7
    #pragma unroll
    for (int j = 0; j < 4; j++) {
        const int e = y + j * 8;
        t[e][x] = W[(size_t)(e0 + e) * HIDDEN + k0 + x];
    }
    __syncthreads();
    #pragma unroll
    for (int j = 0; j < 4; j++) {
        const int k = y + j * 8;
        g_Wt[(size_t)(k0 + k) * NEXP + e0 + x] = t[x][k];
    }
}

// One CTA: 64 tokens x 128 experts. Thread (tx=tid&15, ty=tid>>4) owns
// tokens [ty*8, ty*8+8) x experts [tx*8, tx*8+8) -> 8x8 register tile,
// acc packed 2-experts-per-u64 for FFMA2. Half-warp (width 16) = 8 full
// token rows -> register top-k with shuffles.
__global__ __launch_bounds__(THREADS, 3)
void router_topk_kernel(const float* __restrict__ h,
                        const float* __restrict__ bias,
                        float* __restrict__ outI,
                        float* __restrict__ outW)
{
    extern __shared__ float smem[];
    float* sm_As   = smem;                      // [2][BM][BKP]
    float* sm_Bs   = smem + 2 * AS_STAGE;       // [2][BK][BNP]
    float* bias_s  = sm_Bs + 2 * BS_STAGE;      // [NEXP]

    const int tid = threadIdx.x;
    const int tx  = tid & 15;
    const int ty  = tid >> 4;
    const int m0  = blockIdx.x * BM;

    bias_s[tid] = bias[tid];

    u64 acc[8][4];
    #pragma unroll
    for (int i = 0; i < 8; i++)
        #pragma unroll
        for (int p = 0; p < 4; p++) acc[i][p] = pk2(0.f, 0.f);

    // A loader slots: 512 float4-chunks/stage, 4 per thread. m=c>>3, kq=c&7.
    int aM[4], aKq[4];
    #pragma unroll
    for (int j = 0; j < 4; j++) { int c = tid + THREADS * j; aM[j] = c >> 3; aKq[j] = c & 7; }
    // B cp.async slots: 1024 chunks/stage, 8 per thread. k=c>>5, e4=c&31.
    int bK[8], bE4[8];
    #pragma unroll
    for (int j = 0; j < 8; j++) { int c = tid + THREADS * j; bK[j] = c >> 5; bE4[j] = c & 31; }

    const uint32_t smemBsBase = (uint32_t)__cvta_generic_to_shared(sm_Bs);

    float4 aReg[4];

    // ---- Prologue: stage 0 ----
    #pragma unroll
    for (int j = 0; j < 8; j++) {
        uint32_t dst = smemBsBase + (uint32_t)((bK[j] * BNP + bE4[j] * 4) * 4);
        cp16(dst, g_Wt + (size_t)bK[j] * NEXP + bE4[j] * 4);
    }
    CP_COMMIT();
    #pragma unroll
    for (int j = 0; j < 4; j++)
        aReg[j] = *(const float4*)(h + (size_t)(m0 + aM[j]) * HIDDEN + aKq[j] * 4);

    for (int s = 0; s < NSTAGE; s++) {
        const int buf = s & 1;

        CP_WAIT0();                     // B(s) landed
        #pragma unroll
        for (int j = 0; j < 4; j++) {   // scatter A(s): conflict-free STS.32
            AS(buf, aM[j], aKq[j] * 4 + 0) = aReg[j].x;
            AS(buf, aM[j], aKq[j] * 4 + 1) = aReg[j].y;
            AS(buf, aM[j], aKq[j] * 4 + 2) = aReg[j].z;
            AS(buf, aM[j], aKq[j] * 4 + 3) = aReg[j].w;
        }
        __syncthreads();

        // Prefetch stage s+1 into the other buffer (overlaps compute below)
        if (s + 1 < NSTAGE) {
            const int k0n = (s + 1) * BK;
            const int nb  = buf ^ 1;
            #pragma unroll
            for (int j = 0; j < 8; j++) {
                uint32_t dst = smemBsBase +
                    (uint32_t)((nb * BS_STAGE + bK[j] * BNP + bE4[j] * 4) * 4);
                cp16(dst, g_Wt + (size_t)(k0n + bK[j]) * NEXP + bE4[j] * 4);
            }
            #pragma unroll
            for (int j = 0; j < 4; j++)
                aReg[j] = *(const float4*)(h + (size_t)(m0 + aM[j]) * HIDDEN + k0n + aKq[j] * 4);
        }
        CP_COMMIT();                    // (empty group when s+1==NSTAGE)

        // Inner product: 32 FFMA2 per k-step per thread
        #pragma unroll 8
        for (int k = 0; k < BK; k++) {
            const ulonglong2 b0 = *(const ulonglong2*)&BS(buf, k, tx * 8);
            const ulonglong2 b1 = *(const ulonglong2*)&BS(buf, k, tx * 8 + 4);
            #pragma unroll
            for (int i = 0; i < 8; i++) {
                const float av = AS(buf, ty * 8 + i, k);
                const u64 aa = pk2(av, av);
                fma2(acc[i][0], aa, b0.x);
                fma2(acc[i][1], aa, b0.y);
                fma2(acc[i][2], aa, b1.x);
                fma2(acc[i][3], aa, b1.y);
            }
        }
        __syncthreads();
    }

    // ---- Epilogue: sigmoid + bias, top-8 (tie -> lowest index), normalize ----
    const unsigned FULL = 0xffffffffu;
    #pragma unroll
    for (int i = 0; i < 8; i++) {
        float sc[8];
        #pragma unroll
        for (int p = 0; p < 4; p++) {
            float lo, hi; upk2(acc[i][p], lo, hi);
            sc[2 * p] = lo; sc[2 * p + 1] = hi;
        }
        // corrected score = sigmoid(logit) + bias (raw = corrected - bias)
        #pragma unroll
        for (int j = 0; j < 8; j++) {
            float sig = 1.0f / (1.0f + expf(-sc[j]));
            sc[j] = sig + bias_s[tx * 8 + j];
        }

        float rem[8];
        #pragma unroll
        for (int j = 0; j < 8; j++) rem[j] = sc[j];

        int   topi[TOPK];
        float topraw[TOPK];
        float denom = 1e-20f;

        #pragma unroll
        for (int sel = 0; sel < TOPK; sel++) {
            float bv = -3.4e38f; int bi = NEXP;
            #pragma unroll
            for (int j = 0; j < 8; j++)
                if (rem[j] > bv) { bv = rem[j]; bi = tx * 8 + j; }
            #pragma unroll
            for (int off = 8; off; off >>= 1) {
                float ov = __shfl_xor_sync(FULL, bv, off, 16);
                int   oi = __shfl_xor_sync(FULL, bi, off, 16);
                if (ov > bv || (ov == bv && oi < bi)) { bv = ov; bi = oi; }
            }
            topi[sel]   = bi;
            float raw   = bv - bias_s[bi];
            topraw[sel] = raw;
            denom      += raw;
            const int lj = bi - tx * 8;
            if (lj >= 0 && lj < 8) rem[lj] = -3.4e38f;
        }

        if (tx == 0) {
            const size_t t = (size_t)(m0 + ty * 8 + i);
            const float inv = 1.0f / denom;
            #pragma unroll
            for (int sel = 0; sel < TOPK; sel++) {
                outI[t * TOPK + sel] = (float)topi[sel];
                outW[t * TOPK + sel] = topraw[sel] * inv;
            }
        }
    }
}

extern "C" void kernel_launch(void* const* d_in, const int* in_sizes, int n_in,
                              void* d_out, int out_size)
{
    const float* h    = (const float*)d_in[0];   // hidden_states [B,S,H] fp32
    const float* W    = (const float*)d_in[1];   // weight [E,H] fp32
    const float* bias = (const float*)d_in[2];   // e_score_correction_bias [E]

    const int T = in_sizes[0] / HIDDEN;          // 16384 tokens

    float* out  = (float*)d_out;
    float* outI = out;                           // indices as fp32
    float* outW = out + (size_t)T * TOPK;        // weights

    // 1) transpose W -> g_Wt (k-major), once per launch
    dim3 tgrid(HIDDEN / 32, NEXP / 32);
    transpose_w_kernel<<<tgrid, 256>>>(W);

    // 2) fused GEMM + sigmoid + top-k
    static int smem_set = 0;
    if (!smem_set) {
        cudaFuncSetAttribute(router_topk_kernel,
                             cudaFuncAttributeMaxDynamicSharedMemorySize,
                             SMEM_FLOATS * sizeof(float));
        smem_set = 1;
    }
    router_topk_kernel<<<T / BM, THREADS, SMEM_FLOATS * sizeof(float)>>>(h, bias, outI, outW);
}